// round 7
// baseline (speedup 1.0000x reference)
#include <cuda_runtime.h>

// PatchChamferDistance: B=32, G=64, P=256, D=3 (fp32)
// d2[i][j] = max(|p_i|^2 + |q_j|^2 - 2 p_i.q_j, 0)
// out = mean_patch( mean_i min_j d2 + mean_j min_i d2 )
//
// R7: JOINT scan — compute each (i,j) ONCE, feed both row-min (forward)
// and col-min (backward).  1 patch / 128-thr CTA.
//   warp w: cols [64w, 64w+64)   lane l: rows [8l, 8l+8)
// Rows (pred) pair-packed in regs; col operand duplicated in smem:
//   scA[j] = {-2qx,-2qx,-2qy,-2qy}, scB[j] = {-2qz,-2qz, qw, qw}
// chain: acc = add2( fma2(Z2,B.x, fma2(Y2,A.y, fma2(X2,A.x, B.y))), W2 )
//   halves = full d2 (pre-clamp) for rows (2k,2k+1) at col j.
// rowmin: per-lane regs -> smem partials -> cross-warp min at end.
// colmin: per-thread tree over 8 rows, then warp bfly min (all 256 rows
// of a col live in one warp), lane 0 accumulates clamped sum.

#define BGQ  2048
#define NP   256
#define T    128
#define INF  3.402823e38f

typedef unsigned long long u64;

__device__ __forceinline__ u64 pk2(float a, float b) {
    u64 r;
    asm("mov.b64 %0, {%1, %2};" : "=l"(r) : "f"(a), "f"(b));
    return r;
}
__device__ __forceinline__ u64 fma2(u64 a, u64 b, u64 c) {
    u64 d;
    asm("fma.rn.f32x2 %0, %1, %2, %3;" : "=l"(d) : "l"(a), "l"(b), "l"(c));
    return d;
}
__device__ __forceinline__ u64 add2(u64 a, u64 b) {
    u64 d;
    asm("add.rn.f32x2 %0, %1, %2;" : "=l"(d) : "l"(a), "l"(b));
    return d;
}
__device__ __forceinline__ void upk2(u64 v, float& lo, float& hi) {
    asm("mov.b64 {%0, %1}, %2;" : "=f"(lo), "=f"(hi) : "l"(v));
}

__global__ void pcd_zero_kernel(float* out) { out[0] = 0.0f; }

__global__ __launch_bounds__(T)
void pcd_chamfer_kernel(const float* __restrict__ pred,
                        const float* __restrict__ tgt,
                        float* __restrict__ out)
{
    __shared__ float4     srow[NP];       // pred rows: {x,y,z,w}
    __shared__ ulonglong2 scA[NP];        // tgt cols: {-2x,-2x,-2y,-2y}
    __shared__ ulonglong2 scB[NP];        // tgt cols: {-2z,-2z, w, w}
    __shared__ float      rowpart[4][NP]; // per-warp rowmin partials
    __shared__ float      wsum[T / 32];

    const int t     = threadIdx.x;
    const int patch = blockIdx.x;

    const float* pb = pred + (size_t)patch * NP * 3;
    const float* qb = tgt  + (size_t)patch * NP * 3;

    // phase 1: cooperative load, 2 points of each cloud per thread
#pragma unroll
    for (int r = 0; r < 2; r++) {
        int i = t + T * r;
        float x = pb[i * 3 + 0], y = pb[i * 3 + 1], z = pb[i * 3 + 2];
        srow[i] = make_float4(x, y, z, x * x + y * y + z * z);

        x = qb[i * 3 + 0]; y = qb[i * 3 + 1]; z = qb[i * 3 + 2];
        float w = x * x + y * y + z * z;
        scA[i] = make_ulonglong2(pk2(-2.f * x, -2.f * x), pk2(-2.f * y, -2.f * y));
        scB[i] = make_ulonglong2(pk2(-2.f * z, -2.f * z), pk2(w, w));
    }
    __syncthreads();

    const int w = t >> 5;      // warp -> col group
    const int l = t & 31;      // lane -> row group

    // own 8 pred rows (8l .. 8l+7), packed pairwise
    u64 X2[4], Y2[4], Z2[4], W2[4];
#pragma unroll
    for (int k = 0; k < 4; k++) {
        float4 r0 = srow[8 * l + 2 * k];
        float4 r1 = srow[8 * l + 2 * k + 1];
        X2[k] = pk2(r0.x, r1.x);
        Y2[k] = pk2(r0.y, r1.y);
        Z2[k] = pk2(r0.z, r1.z);
        W2[k] = pk2(r0.w, r1.w);
    }

    float rmn[8] = {INF, INF, INF, INF, INF, INF, INF, INF};
    float colacc = 0.f;
    const int c0 = w * 64;

#pragma unroll 2
    for (int jc = 0; jc < 64; jc++) {
        const int j = c0 + jc;
        ulonglong2 a = scA[j];     // warp-uniform -> LDS broadcast
        ulonglong2 b = scB[j];

        float d[8];
#pragma unroll
        for (int k = 0; k < 4; k++) {
            u64 acc = fma2(X2[k], a.x, b.y);
            acc = fma2(Y2[k], a.y, acc);
            acc = fma2(Z2[k], b.x, acc);
            acc = add2(acc, W2[k]);          // full d2 (pre-clamp)
            upk2(acc, d[2 * k], d[2 * k + 1]);
        }

        // rowmin updates (8)
#pragma unroll
        for (int r = 0; r < 8; r++)
            rmn[r] = fminf(rmn[r], d[r]);

        // thread-local colmin tree over own 8 rows (7)
        float m01 = fminf(d[0], d[1]);
        float m23 = fminf(d[2], d[3]);
        float m45 = fminf(d[4], d[5]);
        float m67 = fminf(d[6], d[7]);
        float m = fminf(fminf(m01, m23), fminf(m45, m67));

        // warp colmin over all 256 rows (bfly: every lane gets result)
#pragma unroll
        for (int o = 16; o > 0; o >>= 1)
            m = fminf(m, __shfl_xor_sync(0xffffffffu, m, o));

        if (l == 0) colacc += fmaxf(m, 0.f);
    }

    // rowmin partials -> smem
#pragma unroll
    for (int r = 0; r < 8; r++)
        rowpart[w][8 * l + r] = rmn[r];
    __syncthreads();

    // cross-warp rowmin: thread t finishes rows 2t, 2t+1
    float v = colacc;
#pragma unroll
    for (int r = 0; r < 2; r++) {
        int i = 2 * t + r;
        float m = fminf(fminf(rowpart[0][i], rowpart[1][i]),
                        fminf(rowpart[2][i], rowpart[3][i]));
        v += fmaxf(m, 0.f);
    }

    // block reduction
#pragma unroll
    for (int o = 16; o > 0; o >>= 1)
        v += __shfl_down_sync(0xffffffffu, v, o);
    if ((t & 31) == 0) wsum[t >> 5] = v;
    __syncthreads();
    if (t == 0) {
        float s = wsum[0] + wsum[1] + wsum[2] + wsum[3];
        atomicAdd(out, s * (1.0f / ((float)NP * (float)BGQ)));
    }
}

extern "C" void kernel_launch(void* const* d_in, const int* in_sizes, int n_in,
                              void* d_out, int out_size)
{
    const float* pred = (const float*)d_in[0];
    const float* tgt  = (const float*)d_in[1];
    float* out = (float*)d_out;

    pcd_zero_kernel<<<1, 1>>>(out);
    pcd_chamfer_kernel<<<BGQ, T>>>(pred, tgt, out);
}